// round 12
// baseline (speedup 1.0000x reference)
#include <cuda_runtime.h>
#include <cuda_fp16.h>
#include <cstdint>
#include <math.h>

#define NCLU 8
#define DIN  1024
#define DHID 256
#define NTOK 65536
#define RPB  96             // rows per CTA: 64 MMA + 32 HFMA2
#define MROWS 64
#define KT   64             // k per tile
#define NKT  (DIN / KT)     // 16 tiles
#define PADK 72             // padded fp16 row stride (144 B)
#define ROWB (PADK * 2)

// ---- dynamic shared memory layout (byte offsets) ----
#define SM_A0    0                         // 2 x 96 x 144  = 27648
#define SM_B0    27648                     // 2 x 256 x 144 = 73728
#define SM_ACC   101376                    // 8 x 256 x 4   = 8192
#define SM_B1S   109568                    // 256 floats
#define SM_CID   110592                    // 96 ints (+pad)
#define SM_HIST  110976                    // 8 u32
#define SM_TOTAL 111008

// ------------- device scratch (no allocs allowed) -------------
__device__ __half        g_w1h[DHID * DIN];   // row-major [256][1024]
__device__ __half        g_w1t[DIN * DHID];   // transposed [1024][256]
__device__ float         g_segsum[NCLU * DHID];
__device__ unsigned int  g_counts[NCLU];

__device__ __forceinline__ uint32_t p2h(float a, float b) {
    __half2 h = __floats2half2_rn(a, b);
    return *reinterpret_cast<const uint32_t*>(&h);
}
__device__ __forceinline__ uint32_t smem_u32(const void* p) {
    uint32_t a;
    asm("{ .reg .u64 t; cvta.to.shared.u64 t, %1; cvt.u32.u64 %0, t; }"
        : "=r"(a) : "l"(p));
    return a;
}
__device__ __forceinline__ void cp_async16(uint32_t dst, const void* src) {
    asm volatile("cp.async.cg.shared.global [%0], [%1], 16;"
                 :: "r"(dst), "l"(src) : "memory");
}
#define CP_COMMIT() asm volatile("cp.async.commit_group;" ::: "memory")
#define CP_WAIT(n)  asm volatile("cp.async.wait_group %0;" :: "n"(n) : "memory")

__device__ __forceinline__ void mma16816(float c[4], const uint32_t a[4],
                                         uint32_t b0, uint32_t b1) {
    asm volatile(
        "mma.sync.aligned.m16n8k16.row.col.f32.f16.f16.f32 "
        "{%0,%1,%2,%3}, {%4,%5,%6,%7}, {%8,%9}, {%0,%1,%2,%3};"
        : "+f"(c[0]), "+f"(c[1]), "+f"(c[2]), "+f"(c[3])
        : "r"(a[0]), "r"(a[1]), "r"(a[2]), "r"(a[3]), "r"(b0), "r"(b1));
}

// ---------------------------------------------------------------
// Kernel 1a: W1 fp32 -> fp16 row-major, zero accumulators
// ---------------------------------------------------------------
__global__ void prep_kernel(const float* __restrict__ W1) {
    int i = blockIdx.x * blockDim.x + threadIdx.x;   // 65536 float4s
    float4 v = reinterpret_cast<const float4*>(W1)[i];
    uint2 o;
    o.x = p2h(v.x, v.y);
    o.y = p2h(v.z, v.w);
    reinterpret_cast<uint2*>(g_w1h)[i] = o;
    if (i < NCLU * DHID) g_segsum[i] = 0.f;
    if (i < NCLU)        g_counts[i] = 0u;
}

// ---------------------------------------------------------------
// Kernel 1b: W1 [256][1024] -> W1t fp16 [1024][256] (tiled transpose)
//   grid (32, 8), block (32, 8)
// ---------------------------------------------------------------
__global__ void transpose_kernel(const float* __restrict__ W1) {
    __shared__ float tile[32][33];
    int k0 = blockIdx.x * 32, h0 = blockIdx.y * 32;
    for (int dy = threadIdx.y; dy < 32; dy += 8)
        tile[dy][threadIdx.x] = W1[(size_t)(h0 + dy) * DIN + k0 + threadIdx.x];
    __syncthreads();
    for (int dy = threadIdx.y; dy < 32; dy += 8)
        g_w1t[(size_t)(k0 + dy) * DHID + h0 + threadIdx.x] =
            __float2half(tile[threadIdx.x][dy]);
}

// ---------------------------------------------------------------
// Kernel 2: heterogeneous-warp GEMM (96x256x1024 per CTA):
//   warps 0-7 : fp16 mma.sync, rows 0-63 (R9-proven pipeline)
//   warps 8-15: HFMA2 on the FMA pipe, rows 64-95
//   + bias + ReLU + per-cluster segment sum.  grid 683, block 512.
// ---------------------------------------------------------------
__global__ void __launch_bounds__(512, 1)
main_kernel(const float* __restrict__ x,
            const int*   __restrict__ cid_g,
            const float* __restrict__ b1_g) {
    extern __shared__ __align__(16) char smem[];

    char* Abuf = smem + SM_A0;     // [2][96][PADK] fp16
    char* Bbuf = smem + SM_B0;     // [2][256][PADK] fp16
    float*        accS  = reinterpret_cast<float*>(smem + SM_ACC);
    float*        b1s   = reinterpret_cast<float*>(smem + SM_B1S);
    int*          cids  = reinterpret_cast<int*>(smem + SM_CID);
    unsigned int* histS = reinterpret_cast<unsigned int*>(smem + SM_HIST);

    const int tid   = threadIdx.x;
    const int lane  = tid & 31;
    const int wid   = tid >> 5;
    const int rowBase = blockIdx.x * RPB;

    // ---- phase 0 ----
    for (int i = tid; i < NCLU * DHID; i += 512) accS[i] = 0.f;
    if (tid < NCLU) histS[tid] = 0u;
    if (tid < DHID) b1s[tid] = b1_g[tid];
    __syncthreads();
    if (tid < RPB) {
        int grow = rowBase + tid;
        int c = (grow < NTOK) ? cid_g[grow] : 0;
        cids[tid] = c;
        if (grow < NTOK) atomicAdd(&histS[c], 1u);
    }

    // ---- loader lambdas (all 512 threads participate) ----
    // A: 96 rows x 64 k fp32 -> fp16. 384 tasks of 16 floats (tid < 384).
    const int a_r = tid >> 2;        // 0..127 (used when tid<384 -> 0..95)
    const int a_s = tid & 3;
    const uint32_t Bsm = smem_u32(Bbuf);

    float4 xa[4];
    auto ldgA = [&](int t) {
        if (tid < 384) {
            int grow = rowBase + a_r;
            if (grow < NTOK) {
                const float4* p = reinterpret_cast<const float4*>(
                    x + (size_t)grow * DIN + t * KT + a_s * 16);
#pragma unroll
                for (int i = 0; i < 4; ++i) xa[i] = p[i];
            } else {
#pragma unroll
                for (int i = 0; i < 4; ++i) xa[i] = make_float4(0.f, 0.f, 0.f, 0.f);
            }
        }
    };
    auto stsA = [&](int b) {
        if (tid < 384) {
            char* Ab = Abuf + b * (RPB * ROWB);
            uint4 pk;
            pk.x = p2h(xa[0].x, xa[0].y);  pk.y = p2h(xa[0].z, xa[0].w);
            pk.z = p2h(xa[1].x, xa[1].y);  pk.w = p2h(xa[1].z, xa[1].w);
            *reinterpret_cast<uint4*>(Ab + a_r * ROWB + a_s * 32) = pk;
            pk.x = p2h(xa[2].x, xa[2].y);  pk.y = p2h(xa[2].z, xa[2].w);
            pk.z = p2h(xa[3].x, xa[3].y);  pk.w = p2h(xa[3].z, xa[3].w);
            *reinterpret_cast<uint4*>(Ab + a_r * ROWB + a_s * 32 + 16) = pk;
        }
    };
    // B: 256 rows x 64 k fp16 = 2048 16B chunks; 4 per thread.
    auto cpB = [&](int t, int b) {
        uint32_t base = Bsm + b * (DHID * ROWB);
#pragma unroll
        for (int i = 0; i < 4; ++i) {
            int id = tid + i * 512;
            int r = id >> 3, s = id & 7;
            cp_async16(base + r * ROWB + s * 16,
                       g_w1h + (size_t)r * DIN + t * KT + s * 8);
        }
        CP_COMMIT();
    };

    if (wid < 8) {
        // ================= MMA path (rows 0..63) =================
        const int mBase = (wid >> 2) * 32;   // 0 or 32
        const int nBase = (wid & 3) * 64;    // 0/64/128/192
        const int fr  = lane >> 2;
        const int fc2 = (lane & 3) << 1;

        float acc[2][8][4];
#pragma unroll
        for (int m = 0; m < 2; ++m)
#pragma unroll
            for (int n = 0; n < 8; ++n)
#pragma unroll
                for (int q = 0; q < 4; ++q) acc[m][n][q] = 0.f;

        ldgA(0);
        cpB(0, 0);
        for (int t = 0; t < NKT; ++t) {
            const int b = t & 1;
            stsA(b);
            if (t + 1 < NKT) { ldgA(t + 1); cpB(t + 1, b ^ 1); CP_WAIT(1); }
            else             { CP_WAIT(0); }
            __syncthreads();

            const __half* As = reinterpret_cast<const __half*>(Abuf + b * (RPB * ROWB));
            const __half* Bs = reinterpret_cast<const __half*>(Bbuf + b * (DHID * ROWB));
#pragma unroll
            for (int ks = 0; ks < 4; ++ks) {
                const int kb = ks * 16;
                uint32_t a[2][4];
#pragma unroll
                for (int m = 0; m < 2; ++m) {
                    const int r = mBase + m * 16 + fr;
                    const int c = fc2 + kb;
                    a[m][0] = *reinterpret_cast<const uint32_t*>(&As[r * PADK + c]);
                    a[m][1] = *reinterpret_cast<const uint32_t*>(&As[(r + 8) * PADK + c]);
                    a[m][2] = *reinterpret_cast<const uint32_t*>(&As[r * PADK + c + 8]);
                    a[m][3] = *reinterpret_cast<const uint32_t*>(&As[(r + 8) * PADK + c + 8]);
                }
#pragma unroll
                for (int n = 0; n < 8; ++n) {
                    const int col = nBase + n * 8 + fr;
                    const int kk  = fc2 + kb;
                    uint32_t b0 = *reinterpret_cast<const uint32_t*>(&Bs[col * PADK + kk]);
                    uint32_t b1 = *reinterpret_cast<const uint32_t*>(&Bs[col * PADK + kk + 8]);
                    mma16816(acc[0][n], a[0], b0, b1);
                    mma16816(acc[1][n], a[1], b0, b1);
                }
            }
            __syncthreads();
        }

        // epilogue (rows always in range)
#pragma unroll
        for (int m = 0; m < 2; ++m) {
            const int r    = mBase + m * 16 + fr;
            const int cid0 = cids[r];
            const int cid1 = cids[r + 8];
#pragma unroll
            for (int n = 0; n < 8; ++n) {
                const int col = nBase + n * 8 + fc2;
                const float bia0 = b1s[col], bia1 = b1s[col + 1];
                atomicAdd(&accS[cid0 * DHID + col],     fmaxf(acc[m][n][0] + bia0, 0.f));
                atomicAdd(&accS[cid0 * DHID + col + 1], fmaxf(acc[m][n][1] + bia1, 0.f));
                atomicAdd(&accS[cid1 * DHID + col],     fmaxf(acc[m][n][2] + bia0, 0.f));
                atomicAdd(&accS[cid1 * DHID + col + 1], fmaxf(acc[m][n][3] + bia1, 0.f));
            }
        }
    } else {
        // ================= HFMA2 path (rows 64..95) =================
        const int hfw = wid - 8;
        const int r0  = MROWS + hfw * 4;     // local row base
        const int c0  = lane * 8;            // col base (8 contiguous cols)

        __half2 acc2[4][4];
        float   accF[4][8];
#pragma unroll
        for (int r = 0; r < 4; ++r) {
#pragma unroll
            for (int c = 0; c < 4; ++c) acc2[r][c] = __float2half2_rn(0.f);
#pragma unroll
            for (int j = 0; j < 8; ++j) accF[r][j] = 0.f;
        }

        ldgA(0);
        cpB(0, 0);
        for (int t = 0; t < NKT; ++t) {
            const int b = t & 1;
            stsA(b);
            if (t + 1 < NKT) { ldgA(t + 1); cpB(t + 1, b ^ 1); CP_WAIT(1); }
            else             { CP_WAIT(0); }
            __syncthreads();

            const __half* As16 = reinterpret_cast<const __half*>(Abuf + b * (RPB * ROWB));
            const __half* wt   = g_w1t + (size_t)(t * KT) * DHID + c0;
#pragma unroll 4
            for (int k = 0; k < KT; ++k) {
                uint4 bv = *reinterpret_cast<const uint4*>(wt + (size_t)k * DHID);
                __half2 b2[4];
                b2[0] = *reinterpret_cast<__half2*>(&bv.x);
                b2[1] = *reinterpret_cast<__half2*>(&bv.y);
                b2[2] = *reinterpret_cast<__half2*>(&bv.z);
                b2[3] = *reinterpret_cast<__half2*>(&bv.w);
                __half2 a2[4];
#pragma unroll
                for (int r = 0; r < 4; ++r)
                    a2[r] = __half2half2(As16[(r0 + r) * PADK + k]);
#pragma unroll
                for (int r = 0; r < 4; ++r)
#pragma unroll
                    for (int c = 0; c < 4; ++c)
                        acc2[r][c] = __hfma2(a2[r], b2[c], acc2[r][c]);
            }
            // per-tile flush to fp32 (bounds fp16 accumulation depth)
#pragma unroll
            for (int r = 0; r < 4; ++r)
#pragma unroll
                for (int c = 0; c < 4; ++c) {
                    float2 f = __half22float2(acc2[r][c]);
                    accF[r][2 * c]     += f.x;
                    accF[r][2 * c + 1] += f.y;
                    acc2[r][c] = __float2half2_rn(0.f);
                }
            __syncthreads();
        }

        // epilogue (guard OOB rows of the last CTA)
#pragma unroll
        for (int r = 0; r < 4; ++r) {
            const int lrow = r0 + r;
            const int grow = rowBase + lrow;
            if (grow < NTOK) {
                const int cid = cids[lrow];
#pragma unroll
                for (int j = 0; j < 8; ++j) {
                    const int col = c0 + j;
                    atomicAdd(&accS[cid * DHID + col],
                              fmaxf(accF[r][j] + b1s[col], 0.f));
                }
            }
        }
    }
    __syncthreads();

    // ---- flush to global ----
    for (int i = tid; i < NCLU * DHID; i += 512)
        atomicAdd(&g_segsum[i], accS[i]);
    if (tid < NCLU) atomicAdd(&g_counts[tid], histS[tid]);
}

// ---------------------------------------------------------------
// Kernel 3: cluster means + gated attention + softmax + combine
// ---------------------------------------------------------------
__global__ void __launch_bounds__(256, 1)
finalize_kernel(const float* __restrict__ Wf, const float* __restrict__ bf,
                const float* __restrict__ Wa, const float* __restrict__ ba,
                const float* __restrict__ Wb, const float* __restrict__ bb,
                const float* __restrict__ Wc, const float* __restrict__ bc,
                float* __restrict__ out) {
    __shared__ float hc[NCLU][DHID];
    __shared__ float hp[NCLU][DHID];
    __shared__ float ag[NCLU][DHID];
    __shared__ float prob[NCLU];

    const int j = threadIdx.x;

#pragma unroll
    for (int k = 0; k < NCLU; ++k) {
        float cnt = fmaxf((float)g_counts[k], 1.0f);
        hc[k][j] = g_segsum[k * DHID + j] / cnt;
    }
    __syncthreads();

    {   // h_path = relu(hc @ Wf^T + bf)
        float acc[NCLU];
        float bias = bf[j];
#pragma unroll
        for (int k = 0; k < NCLU; ++k) acc[k] = bias;
#pragma unroll 4
        for (int d = 0; d < DHID; ++d) {
            float wv = Wf[j * DHID + d];
#pragma unroll
            for (int k = 0; k < NCLU; ++k) acc[k] += wv * hc[k][d];
        }
#pragma unroll
        for (int k = 0; k < NCLU; ++k) hp[k][j] = fmaxf(acc[k], 0.f);
    }
    __syncthreads();

    {   // a = tanh(hp@Wa^T+ba), g = sigmoid(hp@Wb^T+bb), ag = a*g
        float accA[NCLU], accB[NCLU];
        float biasA = ba[j], biasB = bb[j];
#pragma unroll
        for (int k = 0; k < NCLU; ++k) { accA[k] = biasA; accB[k] = biasB; }
#pragma unroll 4
        for (int d = 0; d < DHID; ++d) {
            float wa = Wa[j * DHID + d];
            float wb = Wb[j * DHID + d];
#pragma unroll
            for (int k = 0; k < NCLU; ++k) {
                float h = hp[k][d];
                accA[k] += wa * h;
                accB[k] += wb * h;
            }
        }
#pragma unroll
        for (int k = 0; k < NCLU; ++k) {
            float a = tanhf(accA[k]);
            float g = 1.0f / (1.0f + expf(-accB[k]));
            ag[k][j] = a * g;
        }
    }
    __syncthreads();

    if (j < NCLU) {
        float s = bc[0];
#pragma unroll 4
        for (int d = 0; d < DHID; ++d) s += Wc[d] * ag[j][d];
        prob[j] = s;
    }
    __syncthreads();
    if (j == 0) {
        float mx = prob[0];
#pragma unroll
        for (int k = 1; k < NCLU; ++k) mx = fmaxf(mx, prob[k]);
        float sum = 0.f, e[NCLU];
#pragma unroll
        for (int k = 0; k < NCLU; ++k) { e[k] = expf(prob[k] - mx); sum += e[k]; }
#pragma unroll
        for (int k = 0; k < NCLU; ++k) prob[k] = e[k] / sum;
    }
    __syncthreads();

    float o = 0.f;
#pragma unroll
    for (int k = 0; k < NCLU; ++k) o += prob[k] * hp[k][j];
    out[j] = o;
}

// ---------------------------------------------------------------
extern "C" void kernel_launch(void* const* d_in, const int* in_sizes, int n_in,
                              void* d_out, int out_size) {
    const float* x   = (const float*)d_in[0];
    const int*   cid = (const int*)  d_in[1];
    const float* W1  = (const float*)d_in[2];
    const float* b1  = (const float*)d_in[3];
    const float* Wf  = (const float*)d_in[4];
    const float* bf  = (const float*)d_in[5];
    const float* Wa  = (const float*)d_in[6];
    const float* ba  = (const float*)d_in[7];
    const float* Wb  = (const float*)d_in[8];
    const float* bb  = (const float*)d_in[9];
    const float* Wc  = (const float*)d_in[10];
    const float* bc  = (const float*)d_in[11];
    float* out = (float*)d_out;

    cudaFuncSetAttribute(main_kernel,
                         cudaFuncAttributeMaxDynamicSharedMemorySize, SM_TOTAL);

    prep_kernel<<<256, 256>>>(W1);
    transpose_kernel<<<dim3(32, 8), dim3(32, 8)>>>(W1);
    main_kernel<<<(NTOK + RPB - 1) / RPB, 512, SM_TOTAL>>>(x, cid, b1);
    finalize_kernel<<<1, 256>>>(Wf, bf, Wa, ba, Wb, bb, Wc, bc, out);
}

// round 14
// speedup vs baseline: 3.2452x; 3.2452x over previous
#include <cuda_runtime.h>
#include <cuda_bf16.h>
#include <cstdint>
#include <math.h>

#define NCLU 8
#define DIN  1024
#define DHID 256
#define NTOK 65536
#define RPB  64             // rows per CTA
#define KT   64             // k per tile
#define NKT  (DIN / KT)     // 16 tiles
#define PADK 72             // padded bf16 row stride (144 B, 16B-aligned)
#define ROWB (PADK * 2)     // 144 bytes per row

// ---- main kernel dynamic shared memory layout (byte offsets) ----
#define SM_A0    0                         // 2 x 64 x 144  = 18432
#define SM_B0    18432                     // 2 x 256 x 144 = 73728
#define SM_ACC   92160                     // 8 x 256 x 4   = 8192
#define SM_B1S   100352                    // 256 floats
#define SM_CID   101376                    // 64 ints
#define SM_HIST  101632                    // 8 u32
#define SM_TOTAL 101664

// ---- finalize kernel dynamic smem (float offsets) ----
#define FZ_TA    0                         // 256 x 33 = 8448
#define FZ_TB    8448                      // 256 x 33 = 8448
#define FZ_HC    16896                     // 8 x 256
#define FZ_HP    18944                     // 8 x 256
#define FZ_AG    20992                     // 8 x 256
#define FZ_PR    23040                     // 8
#define FZ_BYTES ((23040 + 8) * 4)         // 92192 B

// ------------- device scratch (no allocs allowed) -------------
__device__ __nv_bfloat16 g_w1b[DHID * DIN];
__device__ float         g_segsum[NCLU * DHID];
__device__ unsigned int  g_counts[NCLU];

__device__ __forceinline__ uint32_t pack2(float a, float b) {
    __nv_bfloat162 h = __floats2bfloat162_rn(a, b);
    return *reinterpret_cast<const uint32_t*>(&h);
}

__device__ __forceinline__ uint32_t smem_u32(const void* p) {
    uint32_t a;
    asm("{ .reg .u64 t; cvta.to.shared.u64 t, %1; cvt.u32.u64 %0, t; }"
        : "=r"(a) : "l"(p));
    return a;
}

__device__ __forceinline__ void cp_async16(uint32_t dst, const void* src) {
    asm volatile("cp.async.cg.shared.global [%0], [%1], 16;"
                 :: "r"(dst), "l"(src) : "memory");
}
#define CP_COMMIT() asm volatile("cp.async.commit_group;" ::: "memory")
#define CP_WAIT(n)  asm volatile("cp.async.wait_group %0;" :: "n"(n) : "memory")

__device__ __forceinline__ void mma16816(float c[4], const uint32_t a[4],
                                         uint32_t b0, uint32_t b1) {
    asm volatile(
        "mma.sync.aligned.m16n8k16.row.col.f32.bf16.bf16.f32 "
        "{%0,%1,%2,%3}, {%4,%5,%6,%7}, {%8,%9}, {%0,%1,%2,%3};"
        : "+f"(c[0]), "+f"(c[1]), "+f"(c[2]), "+f"(c[3])
        : "r"(a[0]), "r"(a[1]), "r"(a[2]), "r"(a[3]), "r"(b0), "r"(b1));
}

// ---------------------------------------------------------------
// Kernel 1: W1 fp32 -> bf16 (vectorized), zero accumulators
// ---------------------------------------------------------------
__global__ void prep_kernel(const float* __restrict__ W1) {
    int i = blockIdx.x * blockDim.x + threadIdx.x;   // 65536 float4s
    float4 v = reinterpret_cast<const float4*>(W1)[i];
    uint2 o;
    o.x = pack2(v.x, v.y);
    o.y = pack2(v.z, v.w);
    reinterpret_cast<uint2*>(g_w1b)[i] = o;
    if (i < NCLU * DHID) g_segsum[i] = 0.f;
    if (i < NCLU)        g_counts[i] = 0u;
}

// ---------------------------------------------------------------
// Kernel 2: pipelined mma.sync GEMM (64x256x1024 per CTA) +
//           bias + ReLU + per-cluster segment sum.
//   grid 1024, block 256 (8 warps, 2x4 warp grid, warp tile 32x64)
//   2 CTAs per SM.  (Verbatim from the passing R9 kernel.)
// ---------------------------------------------------------------
__global__ void __launch_bounds__(256, 2)
main_kernel(const float* __restrict__ x,
            const int*   __restrict__ cid_g,
            const float* __restrict__ b1_g) {
    extern __shared__ __align__(16) char smem[];

    char* Abuf = smem + SM_A0;     // [2][64][PADK] bf16
    char* Bbuf = smem + SM_B0;     // [2][256][PADK] bf16
    float*        accS  = reinterpret_cast<float*>(smem + SM_ACC);
    float*        b1s   = reinterpret_cast<float*>(smem + SM_B1S);
    int*          cids  = reinterpret_cast<int*>(smem + SM_CID);
    unsigned int* histS = reinterpret_cast<unsigned int*>(smem + SM_HIST);

    const int tid   = threadIdx.x;
    const int lane  = tid & 31;
    const int wid   = tid >> 5;
    const int mBase = (wid >> 2) * 32;       // 0 or 32
    const int nBase = (wid & 3) * 64;        // 0/64/128/192
    const int rowBase = blockIdx.x * RPB;

    // ---- phase 0 ----
    for (int i = tid; i < NCLU * DHID; i += 256) accS[i] = 0.f;
    if (tid < NCLU) histS[tid] = 0u;
    if (tid < DHID) b1s[tid] = b1_g[tid];
    __syncthreads();
    if (tid < RPB) {
        int c = cid_g[rowBase + tid];
        cids[tid] = c;
        atomicAdd(&histS[c], 1u);
    }

    // ---- load-task geometry ----
    const int a_r0 = tid >> 3,         a_s0 = tid & 7;
    const int a_r1 = (tid + 256) >> 3, a_s1 = (tid + 256) & 7;
    const uint32_t Bsm = smem_u32(Bbuf);

    float4 xa[2][2];
    auto ldgA = [&](int t) {
        const float* xp = x + (size_t)rowBase * DIN + t * KT;
        const float4* p0 = reinterpret_cast<const float4*>(xp + (size_t)a_r0 * DIN + a_s0 * 8);
        xa[0][0] = p0[0];  xa[0][1] = p0[1];
        const float4* p1 = reinterpret_cast<const float4*>(xp + (size_t)a_r1 * DIN + a_s1 * 8);
        xa[1][0] = p1[0];  xa[1][1] = p1[1];
    };
    auto stsA = [&](int b) {
        char* Ab = Abuf + b * (RPB * ROWB);
        uint4 pk;
        pk.x = pack2(xa[0][0].x, xa[0][0].y);
        pk.y = pack2(xa[0][0].z, xa[0][0].w);
        pk.z = pack2(xa[0][1].x, xa[0][1].y);
        pk.w = pack2(xa[0][1].z, xa[0][1].w);
        *reinterpret_cast<uint4*>(Ab + a_r0 * ROWB + a_s0 * 16) = pk;
        pk.x = pack2(xa[1][0].x, xa[1][0].y);
        pk.y = pack2(xa[1][0].z, xa[1][0].w);
        pk.z = pack2(xa[1][1].x, xa[1][1].y);
        pk.w = pack2(xa[1][1].z, xa[1][1].w);
        *reinterpret_cast<uint4*>(Ab + a_r1 * ROWB + a_s1 * 16) = pk;
    };
    auto cpB = [&](int t, int b) {
        uint32_t base = Bsm + b * (DHID * ROWB);
#pragma unroll
        for (int i = 0; i < 8; ++i) {
            int id = tid + i * 256;
            int r = id >> 3, s = id & 7;
            cp_async16(base + r * ROWB + s * 16,
                       g_w1b + (size_t)r * DIN + t * KT + s * 8);
        }
        CP_COMMIT();
    };

    float acc[2][8][4];
#pragma unroll
    for (int m = 0; m < 2; ++m)
#pragma unroll
        for (int n = 0; n < 8; ++n)
#pragma unroll
            for (int q = 0; q < 4; ++q) acc[m][n][q] = 0.f;

    const int fr  = lane >> 2;           // 0..7
    const int fc2 = (lane & 3) << 1;     // 0,2,4,6

    // ---- pipelined mainloop (R9-proven structure) ----
    ldgA(0);
    cpB(0, 0);
    for (int t = 0; t < NKT; ++t) {
        const int b = t & 1;
        stsA(b);
        if (t + 1 < NKT) {
            ldgA(t + 1);
            cpB(t + 1, b ^ 1);
            CP_WAIT(1);
        } else {
            CP_WAIT(0);
        }
        __syncthreads();

        const __nv_bfloat16* As = reinterpret_cast<const __nv_bfloat16*>(Abuf + b * (RPB * ROWB));
        const __nv_bfloat16* Bs = reinterpret_cast<const __nv_bfloat16*>(Bbuf + b * (DHID * ROWB));

#pragma unroll
        for (int ks = 0; ks < 4; ++ks) {
            const int kb = ks * 16;
            uint32_t a[2][4];
#pragma unroll
            for (int m = 0; m < 2; ++m) {
                const int r = mBase + m * 16 + fr;
                const int c = fc2 + kb;
                a[m][0] = *reinterpret_cast<const uint32_t*>(&As[r * PADK + c]);
                a[m][1] = *reinterpret_cast<const uint32_t*>(&As[(r + 8) * PADK + c]);
                a[m][2] = *reinterpret_cast<const uint32_t*>(&As[r * PADK + c + 8]);
                a[m][3] = *reinterpret_cast<const uint32_t*>(&As[(r + 8) * PADK + c + 8]);
            }
#pragma unroll
            for (int n = 0; n < 8; ++n) {
                const int col = nBase + n * 8 + fr;
                const int kk  = fc2 + kb;
                uint32_t b0 = *reinterpret_cast<const uint32_t*>(&Bs[col * PADK + kk]);
                uint32_t b1 = *reinterpret_cast<const uint32_t*>(&Bs[col * PADK + kk + 8]);
                mma16816(acc[0][n], a[0], b0, b1);
                mma16816(acc[1][n], a[1], b0, b1);
            }
        }
        __syncthreads();
    }

    // ---- epilogue: bias + ReLU + per-cluster accumulation ----
#pragma unroll
    for (int m = 0; m < 2; ++m) {
        const int r    = mBase + m * 16 + fr;
        const int cid0 = cids[r];
        const int cid1 = cids[r + 8];
#pragma unroll
        for (int n = 0; n < 8; ++n) {
            const int col = nBase + n * 8 + fc2;
            const float bia0 = b1s[col], bia1 = b1s[col + 1];
            float v00 = fmaxf(acc[m][n][0] + bia0, 0.f);
            float v01 = fmaxf(acc[m][n][1] + bia1, 0.f);
            float v10 = fmaxf(acc[m][n][2] + bia0, 0.f);
            float v11 = fmaxf(acc[m][n][3] + bia1, 0.f);
            atomicAdd(&accS[cid0 * DHID + col],     v00);
            atomicAdd(&accS[cid0 * DHID + col + 1], v01);
            atomicAdd(&accS[cid1 * DHID + col],     v10);
            atomicAdd(&accS[cid1 * DHID + col + 1], v11);
        }
    }
    __syncthreads();

    for (int i = tid; i < NCLU * DHID; i += 256)
        atomicAdd(&g_segsum[i], accS[i]);
    if (tid < NCLU) atomicAdd(&g_counts[tid], histS[tid]);
}

// ---------------------------------------------------------------
// Kernel 3: cluster means + gated attention + softmax + combine.
//   Rewritten: coalesced smem-tiled weight loads (chunked over d).
//   1 block, 256 threads, ~92 KB dynamic smem.
// ---------------------------------------------------------------
__global__ void __launch_bounds__(256, 1)
finalize_kernel(const float* __restrict__ Wf, const float* __restrict__ bf,
                const float* __restrict__ Wa, const float* __restrict__ ba,
                const float* __restrict__ Wb, const float* __restrict__ bb,
                const float* __restrict__ Wc, const float* __restrict__ bc,
                float* __restrict__ out) {
    extern __shared__ float fsm[];
    float* tA = fsm + FZ_TA;      // stride-33 tile
    float* tB = fsm + FZ_TB;
    float* hc = fsm + FZ_HC;
    float* hp = fsm + FZ_HP;
    float* ag = fsm + FZ_AG;
    float* pr = fsm + FZ_PR;

    const int tid  = threadIdx.x;
    const int wid  = tid >> 5;
    const int lane = tid & 31;

    // coalesced tile loader: W[0:256][d0:d0+32] -> tile (stride 33)
    auto load_tile = [&](float* tile, const float* W, int d0) {
#pragma unroll
        for (int i = 0; i < 8; ++i) {
            int id  = tid + i * 256;
            int row = id >> 3, f4 = id & 7;
            float4 v = *reinterpret_cast<const float4*>(W + row * DHID + d0 + f4 * 4);
            float* dst = tile + row * 33 + f4 * 4;
            dst[0] = v.x; dst[1] = v.y; dst[2] = v.z; dst[3] = v.w;
        }
    };

    // ---- cluster means (coalesced) ----
#pragma unroll
    for (int k = 0; k < NCLU; ++k) {
        float cnt = fmaxf((float)g_counts[k], 1.0f);
        hc[k * DHID + tid] = g_segsum[k * DHID + tid] / cnt;
    }
    __syncthreads();

    // ---- h_path = relu(hc @ Wf^T + bf) ----
    {
        float acc[NCLU];
        float bias = bf[tid];
#pragma unroll
        for (int k = 0; k < NCLU; ++k) acc[k] = bias;
        for (int d0 = 0; d0 < DHID; d0 += 32) {
            load_tile(tA, Wf, d0);
            __syncthreads();
#pragma unroll 8
            for (int dd = 0; dd < 32; ++dd) {
                float w = tA[tid * 33 + dd];
                int d = d0 + dd;
#pragma unroll
                for (int k = 0; k < NCLU; ++k) acc[k] += w * hc[k * DHID + d];
            }
            __syncthreads();
        }
#pragma unroll
        for (int k = 0; k < NCLU; ++k) hp[k * DHID + tid] = fmaxf(acc[k], 0.f);
    }
    __syncthreads();

    // ---- gated attention: a = tanh(hp@Wa^T+ba), g = sigmoid(hp@Wb^T+bb) ----
    {
        float accA[NCLU], accB[NCLU];
        float biasA = ba[tid], biasB = bb[tid];
#pragma unroll
        for (int k = 0; k < NCLU; ++k) { accA[k] = biasA; accB[k] = biasB; }
        for (int d0 = 0; d0 < DHID; d0 += 32) {
            load_tile(tA, Wa, d0);
            load_tile(tB, Wb, d0);
            __syncthreads();
#pragma unroll 8
            for (int dd = 0; dd < 32; ++dd) {
                float wa = tA[tid * 33 + dd];
                float wb = tB[tid * 33 + dd];
                int d = d0 + dd;
#pragma unroll
                for (int k = 0; k < NCLU; ++k) {
                    float h = hp[k * DHID + d];
                    accA[k] += wa * h;
                    accB[k] += wb * h;
                }
            }
            __syncthreads();
        }
#pragma unroll
        for (int k = 0; k < NCLU; ++k) {
            float a = tanhf(accA[k]);
            float g = 1.0f / (1.0f + expf(-accB[k]));
            ag[k * DHID + tid] = a * g;
        }
    }
    __syncthreads();

    // ---- scores: warp per cluster, coalesced Wc, shfl reduce ----
    {
        float s = 0.f;
#pragma unroll
        for (int i = 0; i < 8; ++i) {
            int d = lane + i * 32;
            s += Wc[d] * ag[wid * DHID + d];
        }
#pragma unroll
        for (int off = 16; off > 0; off >>= 1)
            s += __shfl_xor_sync(0xFFFFFFFFu, s, off);
        if (lane == 0) pr[wid] = s + bc[0];
    }
    __syncthreads();

    // ---- softmax over 8 (thread 0) ----
    if (tid == 0) {
        float mx = pr[0];
#pragma unroll
        for (int k = 1; k < NCLU; ++k) mx = fmaxf(mx, pr[k]);
        float sum = 0.f, e[NCLU];
#pragma unroll
        for (int k = 0; k < NCLU; ++k) { e[k] = expf(pr[k] - mx); sum += e[k]; }
#pragma unroll
        for (int k = 0; k < NCLU; ++k) pr[k] = e[k] / sum;
    }
    __syncthreads();

    // ---- H = sum_k prob[k] * h_path[k] ----
    float o = 0.f;
#pragma unroll
    for (int k = 0; k < NCLU; ++k) o += pr[k] * hp[k * DHID + tid];
    out[tid] = o;
}

// ---------------------------------------------------------------
extern "C" void kernel_launch(void* const* d_in, const int* in_sizes, int n_in,
                              void* d_out, int out_size) {
    const float* x   = (const float*)d_in[0];
    const int*   cid = (const int*)  d_in[1];
    const float* W1  = (const float*)d_in[2];
    const float* b1  = (const float*)d_in[3];
    const float* Wf  = (const float*)d_in[4];
    const float* bf  = (const float*)d_in[5];
    const float* Wa  = (const float*)d_in[6];
    const float* ba  = (const float*)d_in[7];
    const float* Wb  = (const float*)d_in[8];
    const float* bb  = (const float*)d_in[9];
    const float* Wc  = (const float*)d_in[10];
    const float* bc  = (const float*)d_in[11];
    float* out = (float*)d_out;

    cudaFuncSetAttribute(main_kernel,
                         cudaFuncAttributeMaxDynamicSharedMemorySize, SM_TOTAL);
    cudaFuncSetAttribute(finalize_kernel,
                         cudaFuncAttributeMaxDynamicSharedMemorySize, FZ_BYTES);

    prep_kernel<<<256, 256>>>(W1);
    main_kernel<<<1024, 256, SM_TOTAL>>>(x, cid, b1);
    finalize_kernel<<<1, 256, FZ_BYTES>>>(Wf, bf, Wa, ba, Wb, bb, Wc, bc, out);
}

// round 15
// speedup vs baseline: 3.6921x; 1.1377x over previous
#include <cuda_runtime.h>
#include <cuda_bf16.h>
#include <cstdint>
#include <math.h>

#define NCLU 8
#define DIN  1024
#define DHID 256
#define NTOK 65536
#define RPB  64             // rows per CTA
#define KT   64             // k per tile
#define NKT  (DIN / KT)     // 16 tiles
#define PADK 72             // padded bf16 row stride (144 B, 16B-aligned)
#define ROWB (PADK * 2)     // 144 bytes per row

// ---- main kernel dynamic shared memory layout (byte offsets) ----
#define SM_A0    0                         // 2 x 64 x 144  = 18432
#define SM_B0    18432                     // 2 x 256 x 144 = 73728
#define SM_ACC   92160                     // 8 x 256 x 4   = 8192
#define SM_B1S   100352                    // 256 floats
#define SM_CID   101376                    // 64 ints
#define SM_HIST  101632                    // 8 u32
#define SM_TOTAL 101664

// ------------- device scratch (no allocs allowed) -------------
__device__ __nv_bfloat16 g_w1b[DHID * DIN];
__device__ float         g_segsum[NCLU * DHID];
__device__ unsigned int  g_counts[NCLU];
__device__ float         g_hp[NCLU * DHID];
__device__ float         g_ag[NCLU * DHID];

__device__ __forceinline__ uint32_t pack2(float a, float b) {
    __nv_bfloat162 h = __floats2bfloat162_rn(a, b);
    return *reinterpret_cast<const uint32_t*>(&h);
}

__device__ __forceinline__ uint32_t smem_u32(const void* p) {
    uint32_t a;
    asm("{ .reg .u64 t; cvta.to.shared.u64 t, %1; cvt.u32.u64 %0, t; }"
        : "=r"(a) : "l"(p));
    return a;
}

__device__ __forceinline__ void cp_async16(uint32_t dst, const void* src) {
    asm volatile("cp.async.cg.shared.global [%0], [%1], 16;"
                 :: "r"(dst), "l"(src) : "memory");
}
#define CP_COMMIT() asm volatile("cp.async.commit_group;" ::: "memory")
#define CP_WAIT(n)  asm volatile("cp.async.wait_group %0;" :: "n"(n) : "memory")

__device__ __forceinline__ void mma16816(float c[4], const uint32_t a[4],
                                         uint32_t b0, uint32_t b1) {
    asm volatile(
        "mma.sync.aligned.m16n8k16.row.col.f32.bf16.bf16.f32 "
        "{%0,%1,%2,%3}, {%4,%5,%6,%7}, {%8,%9}, {%0,%1,%2,%3};"
        : "+f"(c[0]), "+f"(c[1]), "+f"(c[2]), "+f"(c[3])
        : "r"(a[0]), "r"(a[1]), "r"(a[2]), "r"(a[3]), "r"(b0), "r"(b1));
}

// ---------------------------------------------------------------
// Kernel 1: W1 fp32 -> bf16 (vectorized), zero accumulators
// ---------------------------------------------------------------
__global__ void prep_kernel(const float* __restrict__ W1) {
    int i = blockIdx.x * blockDim.x + threadIdx.x;   // 65536 float4s
    float4 v = reinterpret_cast<const float4*>(W1)[i];
    uint2 o;
    o.x = pack2(v.x, v.y);
    o.y = pack2(v.z, v.w);
    reinterpret_cast<uint2*>(g_w1b)[i] = o;
    if (i < NCLU * DHID) g_segsum[i] = 0.f;
    if (i < NCLU)        g_counts[i] = 0u;
}

// ---------------------------------------------------------------
// Kernel 2: pipelined mma.sync GEMM (64x256x1024 per CTA) +
//           bias + ReLU + per-cluster segment sum.
//   grid 1024, block 256, 2 CTAs/SM.  (Verbatim from passing R9/R13.)
// ---------------------------------------------------------------
__global__ void __launch_bounds__(256, 2)
main_kernel(const float* __restrict__ x,
            const int*   __restrict__ cid_g,
            const float* __restrict__ b1_g) {
    extern __shared__ __align__(16) char smem[];

    char* Abuf = smem + SM_A0;     // [2][64][PADK] bf16
    char* Bbuf = smem + SM_B0;     // [2][256][PADK] bf16
    float*        accS  = reinterpret_cast<float*>(smem + SM_ACC);
    float*        b1s   = reinterpret_cast<float*>(smem + SM_B1S);
    int*          cids  = reinterpret_cast<int*>(smem + SM_CID);
    unsigned int* histS = reinterpret_cast<unsigned int*>(smem + SM_HIST);

    const int tid   = threadIdx.x;
    const int lane  = tid & 31;
    const int wid   = tid >> 5;
    const int mBase = (wid >> 2) * 32;       // 0 or 32
    const int nBase = (wid & 3) * 64;        // 0/64/128/192
    const int rowBase = blockIdx.x * RPB;

    // ---- phase 0 ----
    for (int i = tid; i < NCLU * DHID; i += 256) accS[i] = 0.f;
    if (tid < NCLU) histS[tid] = 0u;
    if (tid < DHID) b1s[tid] = b1_g[tid];
    __syncthreads();
    if (tid < RPB) {
        int c = cid_g[rowBase + tid];
        cids[tid] = c;
        atomicAdd(&histS[c], 1u);
    }

    // ---- load-task geometry ----
    const int a_r0 = tid >> 3,         a_s0 = tid & 7;
    const int a_r1 = (tid + 256) >> 3, a_s1 = (tid + 256) & 7;
    const uint32_t Bsm = smem_u32(Bbuf);

    float4 xa[2][2];
    auto ldgA = [&](int t) {
        const float* xp = x + (size_t)rowBase * DIN + t * KT;
        const float4* p0 = reinterpret_cast<const float4*>(xp + (size_t)a_r0 * DIN + a_s0 * 8);
        xa[0][0] = p0[0];  xa[0][1] = p0[1];
        const float4* p1 = reinterpret_cast<const float4*>(xp + (size_t)a_r1 * DIN + a_s1 * 8);
        xa[1][0] = p1[0];  xa[1][1] = p1[1];
    };
    auto stsA = [&](int b) {
        char* Ab = Abuf + b * (RPB * ROWB);
        uint4 pk;
        pk.x = pack2(xa[0][0].x, xa[0][0].y);
        pk.y = pack2(xa[0][0].z, xa[0][0].w);
        pk.z = pack2(xa[0][1].x, xa[0][1].y);
        pk.w = pack2(xa[0][1].z, xa[0][1].w);
        *reinterpret_cast<uint4*>(Ab + a_r0 * ROWB + a_s0 * 16) = pk;
        pk.x = pack2(xa[1][0].x, xa[1][0].y);
        pk.y = pack2(xa[1][0].z, xa[1][0].w);
        pk.z = pack2(xa[1][1].x, xa[1][1].y);
        pk.w = pack2(xa[1][1].z, xa[1][1].w);
        *reinterpret_cast<uint4*>(Ab + a_r1 * ROWB + a_s1 * 16) = pk;
    };
    auto cpB = [&](int t, int b) {
        uint32_t base = Bsm + b * (DHID * ROWB);
#pragma unroll
        for (int i = 0; i < 8; ++i) {
            int id = tid + i * 256;
            int r = id >> 3, s = id & 7;
            cp_async16(base + r * ROWB + s * 16,
                       g_w1b + (size_t)r * DIN + t * KT + s * 8);
        }
        CP_COMMIT();
    };

    float acc[2][8][4];
#pragma unroll
    for (int m = 0; m < 2; ++m)
#pragma unroll
        for (int n = 0; n < 8; ++n)
#pragma unroll
            for (int q = 0; q < 4; ++q) acc[m][n][q] = 0.f;

    const int fr  = lane >> 2;           // 0..7
    const int fc2 = (lane & 3) << 1;     // 0,2,4,6

    // ---- pipelined mainloop ----
    ldgA(0);
    cpB(0, 0);
    for (int t = 0; t < NKT; ++t) {
        const int b = t & 1;
        stsA(b);
        if (t + 1 < NKT) {
            ldgA(t + 1);
            cpB(t + 1, b ^ 1);
            CP_WAIT(1);
        } else {
            CP_WAIT(0);
        }
        __syncthreads();

        const __nv_bfloat16* As = reinterpret_cast<const __nv_bfloat16*>(Abuf + b * (RPB * ROWB));
        const __nv_bfloat16* Bs = reinterpret_cast<const __nv_bfloat16*>(Bbuf + b * (DHID * ROWB));

#pragma unroll
        for (int ks = 0; ks < 4; ++ks) {
            const int kb = ks * 16;
            uint32_t a[2][4];
#pragma unroll
            for (int m = 0; m < 2; ++m) {
                const int r = mBase + m * 16 + fr;
                const int c = fc2 + kb;
                a[m][0] = *reinterpret_cast<const uint32_t*>(&As[r * PADK + c]);
                a[m][1] = *reinterpret_cast<const uint32_t*>(&As[(r + 8) * PADK + c]);
                a[m][2] = *reinterpret_cast<const uint32_t*>(&As[r * PADK + c + 8]);
                a[m][3] = *reinterpret_cast<const uint32_t*>(&As[(r + 8) * PADK + c + 8]);
            }
#pragma unroll
            for (int n = 0; n < 8; ++n) {
                const int col = nBase + n * 8 + fr;
                const int kk  = fc2 + kb;
                uint32_t b0 = *reinterpret_cast<const uint32_t*>(&Bs[col * PADK + kk]);
                uint32_t b1 = *reinterpret_cast<const uint32_t*>(&Bs[col * PADK + kk + 8]);
                mma16816(acc[0][n], a[0], b0, b1);
                mma16816(acc[1][n], a[1], b0, b1);
            }
        }
        __syncthreads();
    }

    // ---- epilogue: bias + ReLU + per-cluster accumulation ----
#pragma unroll
    for (int m = 0; m < 2; ++m) {
        const int r    = mBase + m * 16 + fr;
        const int cid0 = cids[r];
        const int cid1 = cids[r + 8];
#pragma unroll
        for (int n = 0; n < 8; ++n) {
            const int col = nBase + n * 8 + fc2;
            const float bia0 = b1s[col], bia1 = b1s[col + 1];
            float v00 = fmaxf(acc[m][n][0] + bia0, 0.f);
            float v01 = fmaxf(acc[m][n][1] + bia1, 0.f);
            float v10 = fmaxf(acc[m][n][2] + bia0, 0.f);
            float v11 = fmaxf(acc[m][n][3] + bia1, 0.f);
            atomicAdd(&accS[cid0 * DHID + col],     v00);
            atomicAdd(&accS[cid0 * DHID + col + 1], v01);
            atomicAdd(&accS[cid1 * DHID + col],     v10);
            atomicAdd(&accS[cid1 * DHID + col + 1], v11);
        }
    }
    __syncthreads();

    for (int i = tid; i < NCLU * DHID; i += 256)
        atomicAdd(&g_segsum[i], accS[i]);
    if (tid < NCLU) atomicAdd(&g_counts[tid], histS[tid]);
}

// ---------------------------------------------------------------
// Kernel 3a: hp[k][j] = relu(hc[k] . Wf[j] + bf[j])
//   grid 32, block 256 (8 warps); warp -> one output column j.
// ---------------------------------------------------------------
__global__ void __launch_bounds__(256, 1)
hp_kernel(const float* __restrict__ Wf, const float* __restrict__ bf) {
    __shared__ float hc[NCLU * DHID];
    const int tid  = threadIdx.x;
    const int lane = tid & 31;
    const int w    = tid >> 5;

    for (int i = tid; i < NCLU * DHID; i += 256) {
        int k = i >> 8;
        float cnt = fmaxf((float)g_counts[k], 1.0f);
        hc[i] = g_segsum[i] / cnt;
    }
    __syncthreads();

    const int j = blockIdx.x * 8 + w;
    const float* wrow = Wf + j * DHID;
    float acc[NCLU];
#pragma unroll
    for (int k = 0; k < NCLU; ++k) acc[k] = 0.f;
#pragma unroll
    for (int i = 0; i < 8; ++i) {
        int d = lane + 32 * i;
        float wv = wrow[d];
#pragma unroll
        for (int k = 0; k < NCLU; ++k) acc[k] += wv * hc[k * DHID + d];
    }
#pragma unroll
    for (int k = 0; k < NCLU; ++k)
#pragma unroll
        for (int off = 16; off > 0; off >>= 1)
            acc[k] += __shfl_xor_sync(0xFFFFFFFFu, acc[k], off);
    if (lane == 0) {
        float bias = bf[j];
#pragma unroll
        for (int k = 0; k < NCLU; ++k)
            g_hp[k * DHID + j] = fmaxf(acc[k] + bias, 0.f);
    }
}

// ---------------------------------------------------------------
// Kernel 3b: ag[k][j] = tanh(hp[k].Wa[j]+ba[j]) * sigmoid(hp[k].Wb[j]+bb[j])
//   grid 32, block 256 (8 warps); warp -> one output column j.
// ---------------------------------------------------------------
__global__ void __launch_bounds__(256, 1)
ag_kernel(const float* __restrict__ Wa, const float* __restrict__ ba,
          const float* __restrict__ Wb, const float* __restrict__ bb) {
    __shared__ float hp[NCLU * DHID];
    const int tid  = threadIdx.x;
    const int lane = tid & 31;
    const int w    = tid >> 5;

    for (int i = tid; i < NCLU * DHID; i += 256) hp[i] = g_hp[i];
    __syncthreads();

    const int j = blockIdx.x * 8 + w;
    const float* arow = Wa + j * DHID;
    const float* brow = Wb + j * DHID;
    float accA[NCLU], accB[NCLU];
#pragma unroll
    for (int k = 0; k < NCLU; ++k) { accA[k] = 0.f; accB[k] = 0.f; }
#pragma unroll
    for (int i = 0; i < 8; ++i) {
        int d = lane + 32 * i;
        float wa = arow[d];
        float wb = brow[d];
#pragma unroll
        for (int k = 0; k < NCLU; ++k) {
            float h = hp[k * DHID + d];
            accA[k] += wa * h;
            accB[k] += wb * h;
        }
    }
#pragma unroll
    for (int k = 0; k < NCLU; ++k)
#pragma unroll
        for (int off = 16; off > 0; off >>= 1) {
            accA[k] += __shfl_xor_sync(0xFFFFFFFFu, accA[k], off);
            accB[k] += __shfl_xor_sync(0xFFFFFFFFu, accB[k], off);
        }
    if (lane == 0) {
        float biasA = ba[j], biasB = bb[j];
#pragma unroll
        for (int k = 0; k < NCLU; ++k) {
            float a = tanhf(accA[k] + biasA);
            float g = 1.0f / (1.0f + expf(-(accB[k] + biasB)));
            g_ag[k * DHID + j] = a * g;
        }
    }
}

// ---------------------------------------------------------------
// Kernel 3c: scores + softmax + weighted combine -> out[256]
//   1 block, 256 threads.
// ---------------------------------------------------------------
__global__ void __launch_bounds__(256, 1)
tail_kernel(const float* __restrict__ Wc, const float* __restrict__ bc,
            float* __restrict__ out) {
    __shared__ float pr[NCLU];
    const int tid  = threadIdx.x;
    const int lane = tid & 31;
    const int w    = tid >> 5;

    // warp w computes score for cluster w
    float s = 0.f;
#pragma unroll
    for (int i = 0; i < 8; ++i) {
        int d = lane + 32 * i;
        s += Wc[d] * g_ag[w * DHID + d];
    }
#pragma unroll
    for (int off = 16; off > 0; off >>= 1)
        s += __shfl_xor_sync(0xFFFFFFFFu, s, off);
    if (lane == 0) pr[w] = s + bc[0];
    __syncthreads();

    if (tid == 0) {
        float mx = pr[0];
#pragma unroll
        for (int k = 1; k < NCLU; ++k) mx = fmaxf(mx, pr[k]);
        float sum = 0.f, e[NCLU];
#pragma unroll
        for (int k = 0; k < NCLU; ++k) { e[k] = expf(pr[k] - mx); sum += e[k]; }
#pragma unroll
        for (int k = 0; k < NCLU; ++k) pr[k] = e[k] / sum;
    }
    __syncthreads();

    float o = 0.f;
#pragma unroll
    for (int k = 0; k < NCLU; ++k) o += pr[k] * g_hp[k * DHID + tid];
    out[tid] = o;
}

// ---------------------------------------------------------------
extern "C" void kernel_launch(void* const* d_in, const int* in_sizes, int n_in,
                              void* d_out, int out_size) {
    const float* x   = (const float*)d_in[0];
    const int*   cid = (const int*)  d_in[1];
    const float* W1  = (const float*)d_in[2];
    const float* b1  = (const float*)d_in[3];
    const float* Wf  = (const float*)d_in[4];
    const float* bf  = (const float*)d_in[5];
    const float* Wa  = (const float*)d_in[6];
    const float* ba  = (const float*)d_in[7];
    const float* Wb  = (const float*)d_in[8];
    const float* bb  = (const float*)d_in[9];
    const float* Wc  = (const float*)d_in[10];
    const float* bc  = (const float*)d_in[11];
    float* out = (float*)d_out;

    cudaFuncSetAttribute(main_kernel,
                         cudaFuncAttributeMaxDynamicSharedMemorySize, SM_TOTAL);

    prep_kernel<<<256, 256>>>(W1);
    main_kernel<<<1024, 256, SM_TOTAL>>>(x, cid, b1);
    hp_kernel<<<32, 256>>>(Wf, bf);
    ag_kernel<<<32, 256>>>(Wa, ba, Wb, bb);
    tail_kernel<<<1, 256>>>(Wc, bc, out);
}